// round 15
// baseline (speedup 1.0000x reference)
#include <cuda_runtime.h>
#include <cuda_bf16.h>
#include <cstdint>

// Problem constants
#define BB   16
#define NTOK 577
#define CH   768
#define HH   12
#define DD   64
#define C3   (3 * CH)          // 2304
#define MROW (BB * NTOK)       // 9232
#define NBH  (BB * HH)         // 192

#define LD_S  608              // S row stride (mult of 32 floats = 128B aligned)
#define LD_P  608              // P2 row stride (mult of 32: K-pad for AV GEMM)

// ---------------------------------------------------------------------------
// Scratch (static device globals; zero-initialized; no runtime alloc)
// P2 pad columns [577,608) are NEVER written anywhere: they stay zero from
// module-load init, which the K-padded AV GEMM relies on. Deterministic.
// ---------------------------------------------------------------------------
__device__ __align__(128) float g_qkv[(size_t)MROW * C3];
__device__ __align__(128) float g_S  [(size_t)NBH * NTOK * LD_S];
__device__ __align__(128) float g_P2 [(size_t)NBH * NTOK * LD_P];
__device__ __align__(128) float g_vT [(size_t)NBH * DD * LD_P];
__device__ __align__(128) float g_tmp[(size_t)MROW * CH];
__device__ __align__(128) float g_xr   [(size_t)MROW * CH];
__device__ __align__(128) float g_wqkvr[(size_t)C3 * CH];
__device__ __align__(128) float g_wprojr[(size_t)CH * CH];

__device__ __forceinline__ uint32_t f2tf32(float f) {
    uint32_t r;
    asm("cvt.rna.tf32.f32 %0, %1;" : "=r"(r) : "f"(f));
    return r;
}
__device__ __forceinline__ float rndf(float f) { return __uint_as_float(f2tf32(f)); }

// f32x2 helpers
__device__ __forceinline__ unsigned long long pk2(float lo, float hi) {
    unsigned long long u;
    asm("mov.b64 %0, {%1, %2};" : "=l"(u) : "r"(__float_as_uint(lo)), "r"(__float_as_uint(hi)));
    return u;
}
__device__ __forceinline__ void upk2(unsigned long long u, float& lo, float& hi) {
    uint32_t a, b;
    asm("mov.b64 {%0, %1}, %2;" : "=r"(a), "=r"(b) : "l"(u));
    lo = __uint_as_float(a); hi = __uint_as_float(b);
}
__device__ __forceinline__ unsigned long long fma2(unsigned long long a,
                                                   unsigned long long b,
                                                   unsigned long long c) {
    unsigned long long d;
    asm("fma.rn.f32x2 %0, %1, %2, %3;" : "=l"(d) : "l"(a), "l"(b), "l"(c));
    return d;
}
__device__ __forceinline__ unsigned long long mul2(unsigned long long a,
                                                   unsigned long long b) {
    unsigned long long d;
    asm("mul.rn.f32x2 %0, %1, %2;" : "=l"(d) : "l"(a), "l"(b));
    return d;
}

__device__ __forceinline__ void ldsm4(uint32_t& r0, uint32_t& r1,
                                      uint32_t& r2, uint32_t& r3, uint32_t addr) {
    asm volatile("ldmatrix.sync.aligned.m8n8.x4.shared.b16 {%0,%1,%2,%3}, [%4];"
                 : "=r"(r0), "=r"(r1), "=r"(r2), "=r"(r3) : "r"(addr));
}
__device__ __forceinline__ void cp16(uint32_t saddr, const float* g, bool v) {
    asm volatile("cp.async.cg.shared.global [%0], [%1], 16, %2;"
                 :: "r"(saddr), "l"(g), "r"(v ? 16 : 0));
}

// ---------------------------------------------------------------------------
// Fused elementwise tf32-round copy over three buffers
// ---------------------------------------------------------------------------
__global__ __launch_bounds__(256)
void round_copy3_kernel(const float* __restrict__ a, float* __restrict__ oa, int na4,
                        const float* __restrict__ b, float* __restrict__ ob, int nb4,
                        const float* __restrict__ c, float* __restrict__ oc, int nc4)
{
    int total = na4 + nb4 + nc4;
    int i = blockIdx.x * 256 + threadIdx.x;
    int stride = gridDim.x * 256;
    for (; i < total; i += stride) {
        const float4* src;
        float4* dst;
        int idx = i;
        if (idx < na4) {
            src = reinterpret_cast<const float4*>(a);
            dst = reinterpret_cast<float4*>(oa);
        } else if ((idx -= na4) < nb4) {
            src = reinterpret_cast<const float4*>(b);
            dst = reinterpret_cast<float4*>(ob);
        } else {
            idx -= nb4;
            src = reinterpret_cast<const float4*>(c);
            dst = reinterpret_cast<float4*>(oc);
        }
        float4 v = src[idx];
        v.x = rndf(v.x); v.y = rndf(v.y); v.z = rndf(v.z); v.w = rndf(v.w);
        dst[idx] = v;
    }
}

// ---------------------------------------------------------------------------
// tf32 tensor-core NT GEMM, 3-stage cp.async, ldmatrix fragment loads.
// Smem per stage: row-major [row][128B], chunk index XOR-swizzled by row&7:
//   addr(row, kc) = row*128 + ((kc ^ (row & 7)) << 4)
//   C[m,n] = alpha * sum_k A[m*lda+k] * B[n*ldb+k]  (+ bias[n])
// 256 threads, warps 2(M) x 4(N). BK=32, K % 32 == 0. Inputs tf32-pre-rounded.
// ---------------------------------------------------------------------------
template<int BM, int BN, bool ROUND, int MINCTA>
__global__ __launch_bounds__(256, MINCTA)
void tc_gemm_nt(const float* __restrict__ A, const float* __restrict__ B,
                float* __restrict__ C, const float* __restrict__ bias,
                int M, int Nn, int K, int lda, int ldb, int ldc, float alpha,
                int Hdim,
                long long sAb, long long sAh,
                long long sBb, long long sBh,
                long long sCb, long long sCh)
{
    constexpr int BK = 32;
    constexpr int MI = BM / 2 / 16;
    constexpr int NJ = BN / 4 / 8;
    constexpr int ASTG = BM * 128;        // bytes per A stage
    constexpr int BSTG = BN * 128;        // bytes per B stage

    extern __shared__ uint32_t sm[];
    uint32_t* Asm = sm;                           // 3 stages A
    uint32_t* Bsm = sm + 3 * (ASTG / 4);          // 3 stages B

    const int z  = blockIdx.z;
    const int bb = z / Hdim;
    const int hh = z % Hdim;
    A += bb * sAb + hh * sAh;
    B += bb * sBb + hh * sBh;
    C += bb * sCb + hh * sCh;

    const int m0   = blockIdx.y * BM;
    const int n0   = blockIdx.x * BN;
    const int tid  = threadIdx.x;
    const int wid  = tid >> 5;
    const int lane = tid & 31;
    const int g    = lane >> 2;
    const int t    = lane & 3;
    const int wm   = (wid >> 2) * (BM / 2);
    const int wn   = (wid & 3) * (BN / 4);

    // producer indices
    const int pr  = tid >> 3;             // row 0..31
    const int pkc = tid & 7;              // k-chunk 0..7

    // consumer ldmatrix lane roles
    const int lrowA = (lane & 7) + ((lane >> 3) & 1) * 8;   // A: m within 16
    const int lkcA  = lane >> 4;                            // A: kc parity
    const int lrowB = (lane & 7) + ((lane >> 4) & 1) * 8;   // B: n within 16
    const int lkcB  = (lane >> 3) & 1;                      // B: kc parity

    const uint32_t sA = (uint32_t)__cvta_generic_to_shared(Asm);
    const uint32_t sB = (uint32_t)__cvta_generic_to_shared(Bsm);

    float acc[MI][NJ][4];
#pragma unroll
    for (int i = 0; i < MI; i++)
#pragma unroll
        for (int j = 0; j < NJ; j++)
#pragma unroll
            for (int q = 0; q < 4; q++) acc[i][j][q] = 0.f;

    const int niter = K / BK;

    auto issue = [&](int it) {
        const int k0 = it * BK;
        const int st = it % 3;
        const uint32_t aBase = sA + st * ASTG;
        const uint32_t bBase = sB + st * BSTG;
#pragma unroll
        for (int q = 0; q < BM / 32; q++) {
            int r  = pr + q * 32;
            int gm = m0 + r;
            bool v = gm < M;
            cp16(aBase + (r << 7) + (((pkc ^ (r & 7)) & 7) << 4),
                 A + (long long)(v ? gm : 0) * lda + k0 + pkc * 4, v);
        }
#pragma unroll
        for (int q = 0; q < BN / 32; q++) {
            int r  = pr + q * 32;
            int gn = n0 + r;
            bool v = gn < Nn;
            cp16(bBase + (r << 7) + (((pkc ^ (r & 7)) & 7) << 4),
                 B + (long long)(v ? gn : 0) * ldb + k0 + pkc * 4, v);
        }
        asm volatile("cp.async.commit_group;" ::: "memory");
    };

    issue(0);
    if (niter > 1) issue(1);

    for (int it = 0; it < niter; it++) {
        if (it + 2 <= niter) {
            asm volatile("cp.async.wait_group 1;" ::: "memory");
        } else {
            asm volatile("cp.async.wait_group 0;" ::: "memory");
        }
        __syncthreads();
        if (it + 2 < niter) issue(it + 2);

        const uint32_t aBase = sA + (it % 3) * ASTG;
        const uint32_t bBase = sB + (it % 3) * BSTG;

#pragma unroll
        for (int s = 0; s < 4; s++) {
            uint32_t af[MI][4];
            const int kcA = 2 * s + lkcA;
#pragma unroll
            for (int i = 0; i < MI; i++) {
                int m = wm + i * 16 + lrowA;
                ldsm4(af[i][0], af[i][1], af[i][2], af[i][3],
                      aBase + (m << 7) + (((kcA ^ (m & 7)) & 7) << 4));
            }
            uint32_t bf[NJ][2];
            const int kcB = 2 * s + lkcB;
#pragma unroll
            for (int jp = 0; jp < NJ / 2; jp++) {
                int n = wn + jp * 16 + lrowB;
                // Matrix order: (n0-7,kc even)=b0 lo, (n0-7,kc odd)=b1 lo,
                //               (n8-15,kc even)=b0 hi, (n8-15,kc odd)=b1 hi
                ldsm4(bf[2 * jp][0], bf[2 * jp][1],
                      bf[2 * jp + 1][0], bf[2 * jp + 1][1],
                      bBase + (n << 7) + (((kcB ^ (n & 7)) & 7) << 4));
            }
#pragma unroll
            for (int i = 0; i < MI; i++)
#pragma unroll
                for (int j = 0; j < NJ; j++) {
                    asm volatile(
                        "mma.sync.aligned.m16n8k8.row.col.f32.tf32.tf32.f32 "
                        "{%0,%1,%2,%3}, {%4,%5,%6,%7}, {%8,%9}, {%0,%1,%2,%3};"
                        : "+f"(acc[i][j][0]), "+f"(acc[i][j][1]),
                          "+f"(acc[i][j][2]), "+f"(acc[i][j][3])
                        : "r"(af[i][0]), "r"(af[i][1]), "r"(af[i][2]), "r"(af[i][3]),
                          "r"(bf[j][0]), "r"(bf[j][1]));
                }
        }
        // no trailing __syncthreads: top-of-loop barrier provides WAR safety
    }

    // ---- epilogue ----
#pragma unroll
    for (int i = 0; i < MI; i++) {
        int gm0 = m0 + wm + i * 16 + g;
        int gm1 = gm0 + 8;
#pragma unroll
        for (int j = 0; j < NJ; j++) {
            int gn = n0 + wn + j * 8 + 2 * t;
            float b0 = 0.f, b1 = 0.f;
            if (bias) {
                if (gn < Nn)     b0 = bias[gn];
                if (gn + 1 < Nn) b1 = bias[gn + 1];
            }
            float c0 = acc[i][j][0] * alpha + b0;
            float c1 = acc[i][j][1] * alpha + b1;
            float c2 = acc[i][j][2] * alpha + b0;
            float c3 = acc[i][j][3] * alpha + b1;
            if (ROUND) { c0 = rndf(c0); c1 = rndf(c1); c2 = rndf(c2); c3 = rndf(c3); }
            if (gm0 < M) {
                if (gn + 1 < Nn)
                    *reinterpret_cast<float2*>(C + (long long)gm0 * ldc + gn) = make_float2(c0, c1);
                else if (gn < Nn)
                    C[(long long)gm0 * ldc + gn] = c0;
            }
            if (gm1 < M) {
                if (gn + 1 < Nn)
                    *reinterpret_cast<float2*>(C + (long long)gm1 * ldc + gn) = make_float2(c2, c3);
                else if (gn < Nn)
                    C[(long long)gm1 * ldc + gn] = c2;
            }
        }
    }
}

// ---------------------------------------------------------------------------
// Transpose V: qkv[b,m, 2, h, d] -> vT[b,h, d, m] (ld = LD_P, pad stays 0)
// ---------------------------------------------------------------------------
__global__ __launch_bounds__(256)
void transpose_v_kernel(const float* __restrict__ qkv, float* __restrict__ vT)
{
    __shared__ float tile[32][33];
    const int dBase = (blockIdx.x & 1) * 32;
    const int mBase = blockIdx.y * 32;
    const int bh    = blockIdx.z;
    const int b     = bh / HH;
    const int h     = bh % HH;
    const int tx = threadIdx.x & 31;
    const int ty = threadIdx.x >> 5;

    const float* src = qkv + (long long)b * NTOK * C3 + 2 * CH + h * DD;
#pragma unroll
    for (int i = 0; i < 4; i++) {
        int m = mBase + ty + i * 8;
        if (m < NTOK)
            tile[ty + i * 8][tx] = src[(long long)m * C3 + dBase + tx];
    }
    __syncthreads();

    float* dst = vT + (long long)bh * DD * LD_P;
#pragma unroll
    for (int i = 0; i < 4; i++) {
        int d = dBase + ty + i * 8;
        int m = mBase + tx;
        if (m < NTOK)
            dst[(long long)d * LD_P + m] = tile[tx][ty + i * 8];
    }
}

// ---------------------------------------------------------------------------
// Fused talking-heads (register version, f32x2). P2 pad cols never written.
// ---------------------------------------------------------------------------
#define MIXT 320

__global__ __launch_bounds__(MIXT)
void mix_softmax_kernel(const float* __restrict__ S,
                        const float* __restrict__ Wpre,
                        const float* __restrict__ Wpost,
                        float* __restrict__ P2)
{
    __shared__ unsigned long long w2pre[HH * HH];
    __shared__ unsigned long long w2post[HH * HH];
    __shared__ float red[MIXT / 32][HH];
    __shared__ float smax[HH];
    __shared__ float sinv[HH];

    const int tid  = threadIdx.x;
    const int warp = tid >> 5;
    const int lane = tid & 31;
    const int bn = blockIdx.x;
    const int b  = bn / NTOK;
    const int n  = bn % NTOK;

    if (tid < HH * HH) {
        float wp = Wpre[tid];
        float wq = Wpost[tid];
        w2pre[tid]  = pk2(wp, wp);
        w2post[tid] = pk2(wq, wq);
    }
    __syncthreads();

    const float* Sb = S + ((long long)b * HH * NTOK + n) * LD_S;
    const int m0 = tid;
    const int m1 = tid + MIXT;
    const bool v1 = (m1 < NTOK);

    unsigned long long s2[HH];
#pragma unroll
    for (int h = 0; h < HH; h++) {
        const float* p = Sb + (long long)h * NTOK * LD_S;
        float lo = p[m0];
        float hi = v1 ? p[m1] : 0.f;
        s2[h] = pk2(lo, hi);
    }

    unsigned long long t2[HH];
#pragma unroll
    for (int gg = 0; gg < HH; gg++) {
        unsigned long long accv = 0ull;
#pragma unroll
        for (int h = 0; h < HH; h++)
            accv = fma2(w2pre[gg * HH + h], s2[h], accv);
        t2[gg] = accv;
    }

    float lmax[HH];
#pragma unroll
    for (int gg = 0; gg < HH; gg++) {
        float lo, hi; upk2(t2[gg], lo, hi);
        lmax[gg] = v1 ? fmaxf(lo, hi) : lo;
    }
#pragma unroll
    for (int gg = 0; gg < HH; gg++)
#pragma unroll
        for (int o = 16; o > 0; o >>= 1)
            lmax[gg] = fmaxf(lmax[gg], __shfl_xor_sync(0xffffffffu, lmax[gg], o));
    if (lane == 0)
#pragma unroll
        for (int gg = 0; gg < HH; gg++) red[warp][gg] = lmax[gg];
    __syncthreads();
    if (tid < HH) {
        float mx = red[0][tid];
#pragma unroll
        for (int w = 1; w < MIXT / 32; w++) mx = fmaxf(mx, red[w][tid]);
        smax[tid] = mx;
    }
    __syncthreads();

    float lsum[HH];
#pragma unroll
    for (int gg = 0; gg < HH; gg++) {
        float lo, hi; upk2(t2[gg], lo, hi);
        float el = __expf(lo - smax[gg]);
        float eh = v1 ? __expf(hi - smax[gg]) : 0.f;
        t2[gg] = pk2(el, eh);
        lsum[gg] = el + eh;
    }
#pragma unroll
    for (int gg = 0; gg < HH; gg++)
#pragma unroll
        for (int o = 16; o > 0; o >>= 1)
            lsum[gg] += __shfl_xor_sync(0xffffffffu, lsum[gg], o);
    if (lane == 0)
#pragma unroll
        for (int gg = 0; gg < HH; gg++) red[warp][gg] = lsum[gg];
    __syncthreads();
    if (tid < HH) {
        float s = red[0][tid];
#pragma unroll
        for (int w = 1; w < MIXT / 32; w++) s += red[w][tid];
        sinv[tid] = 1.f / s;
    }
    __syncthreads();

#pragma unroll
    for (int h = 0; h < HH; h++) {
        float iv = sinv[h];
        t2[h] = mul2(t2[h], pk2(iv, iv));
    }

    float* Pb = P2 + ((long long)b * HH * NTOK + n) * LD_P;
#pragma unroll
    for (int gg = 0; gg < HH; gg++) {
        unsigned long long accv = 0ull;
#pragma unroll
        for (int h = 0; h < HH; h++)
            accv = fma2(w2post[gg * HH + h], t2[h], accv);
        float lo, hi; upk2(accv, lo, hi);
        float* q = Pb + (long long)gg * NTOK * LD_P;
        q[m0] = rndf(lo);
        if (v1) q[m1] = rndf(hi);
        // pad cols [577,608) stay zero from static init; never written
    }
}

// ---------------------------------------------------------------------------
// Launch
// ---------------------------------------------------------------------------
extern "C" void kernel_launch(void* const* d_in, const int* in_sizes, int n_in,
                              void* d_out, int out_size)
{
    const float* x     = (const float*)d_in[0];
    const float* Wqkv  = (const float*)d_in[1];
    const float* Wproj = (const float*)d_in[2];
    const float* bproj = (const float*)d_in[3];
    const float* Wpre  = (const float*)d_in[4];
    const float* Wpost = (const float*)d_in[5];
    float* out = (float*)d_out;

    float *qkv, *S, *P2, *vT, *tmp, *xr, *wqkvr, *wprojr;
    cudaGetSymbolAddress((void**)&qkv, g_qkv);
    cudaGetSymbolAddress((void**)&S,   g_S);
    cudaGetSymbolAddress((void**)&P2,  g_P2);
    cudaGetSymbolAddress((void**)&vT,  g_vT);
    cudaGetSymbolAddress((void**)&tmp, g_tmp);
    cudaGetSymbolAddress((void**)&xr,  g_xr);
    cudaGetSymbolAddress((void**)&wqkvr, g_wqkvr);
    cudaGetSymbolAddress((void**)&wprojr, g_wprojr);

    // 0) tf32-round raw inputs (single fused launch)
    round_copy3_kernel<<<1024, 256>>>(
        x, xr, MROW * CH / 4,
        Wqkv, wqkvr, C3 * CH / 4,
        Wproj, wprojr, CH * CH / 4);

    const int smem_qkv   = 3 * (96 + 128) * 128;    // 86016
    const int smem_sc64  = 3 * (128 + 64) * 128;    // 73728
    cudaFuncSetAttribute(tc_gemm_nt<96, 128, true, 2>,
                         cudaFuncAttributeMaxDynamicSharedMemorySize, smem_qkv);
    cudaFuncSetAttribute(tc_gemm_nt<96, 128, false, 2>,
                         cudaFuncAttributeMaxDynamicSharedMemorySize, smem_qkv);
    cudaFuncSetAttribute(tc_gemm_nt<128, 64, false, 3>,
                         cudaFuncAttributeMaxDynamicSharedMemorySize, smem_sc64);
    cudaFuncSetAttribute(tc_gemm_nt<128, 64, true, 3>,
                         cudaFuncAttributeMaxDynamicSharedMemorySize, smem_sc64);

    // 1) QKV GEMM: qkv = round(xr @ Wqkv^T)   [9232 x 2304], K=768, BM=96
    {
        dim3 grid(C3 / 128, (MROW + 95) / 96, 1);
        tc_gemm_nt<96, 128, true, 2><<<grid, 256, smem_qkv>>>(
            xr, wqkvr, qkv, nullptr,
            MROW, C3, CH, CH, CH, C3, 1.0f,
            1, 0, 0, 0, 0, 0, 0);
    }

    // 1.5) Transpose V -> vT[b,h,d,m]
    {
        dim3 grid(2, (NTOK + 31) / 32, NBH);
        transpose_v_kernel<<<grid, 256>>>(qkv, vT);
    }

    // 2) Scores: S = 1/8 * q @ k^T  (batched 192, M=577, N=577, K=64)
    //    BN=64 + 3 CTAs/SM: latency-bound kernel -> more TLP.
    {
        dim3 grid((NTOK + 63) / 64, (NTOK + 127) / 128, NBH);
        tc_gemm_nt<128, 64, false, 3><<<grid, 256, smem_sc64>>>(
            qkv, qkv + CH, S, nullptr,
            NTOK, NTOK, DD,
            C3, C3, LD_S, 0.125f,
            HH,
            (long long)NTOK * C3, DD,
            (long long)NTOK * C3, DD,
            (long long)HH * NTOK * LD_S, (long long)NTOK * LD_S);
    }

    // 3) Fused Wpre-mix -> softmax -> Wpost-mix
    mix_softmax_kernel<<<MROW, MIXT>>>(S, Wpre, Wpost, P2);

    // 4) AV: tmp = round(P2 @ vT^T)   (K padded to 608), MINCTA=3
    {
        dim3 grid(1, (NTOK + 127) / 128, NBH);
        tc_gemm_nt<128, 64, true, 3><<<grid, 256, smem_sc64>>>(
            P2, vT, tmp, nullptr,
            NTOK, DD, LD_P,
            LD_P, LD_P, CH, 1.0f,
            HH,
            (long long)HH * NTOK * LD_P, (long long)NTOK * LD_P,
            (long long)HH * DD * LD_P,   (long long)DD * LD_P,
            (long long)NTOK * CH,        DD);
    }

    // 5) Projection: out = tmp @ Wproj^T + bproj   [9232 x 768], K=768, BM=96
    {
        dim3 grid(CH / 128, (MROW + 95) / 96, 1);
        tc_gemm_nt<96, 128, false, 2><<<grid, 256, smem_qkv>>>(
            tmp, wprojr, out, bproj,
            MROW, CH, CH, CH, CH, CH, 1.0f,
            1, 0, 0, 0, 0, 0, 0);
    }
}

// round 16
// speedup vs baseline: 1.0262x; 1.0262x over previous
#include <cuda_runtime.h>
#include <cuda_bf16.h>
#include <cstdint>

// Problem constants
#define BB   16
#define NTOK 577
#define CH   768
#define HH   12
#define DD   64
#define C3   (3 * CH)          // 2304
#define MROW (BB * NTOK)       // 9232
#define NBH  (BB * HH)         // 192

#define LD_S  608              // S row stride (mult of 32 floats = 128B aligned)
#define LD_P  608              // P2 row stride (mult of 32: K-pad for AV GEMM)

// ---------------------------------------------------------------------------
// Scratch (static device globals; zero-initialized; no runtime alloc)
// P2 pad columns [577,608) are NEVER written anywhere: they stay zero from
// module-load init, which the K-padded AV GEMM relies on. Deterministic.
// ---------------------------------------------------------------------------
__device__ __align__(128) float g_qkv[(size_t)MROW * C3];
__device__ __align__(128) float g_S  [(size_t)NBH * NTOK * LD_S];
__device__ __align__(128) float g_P2 [(size_t)NBH * NTOK * LD_P];
__device__ __align__(128) float g_vT [(size_t)NBH * DD * LD_P];
__device__ __align__(128) float g_tmp[(size_t)MROW * CH];
__device__ __align__(128) float g_xr   [(size_t)MROW * CH];
__device__ __align__(128) float g_wqkvr[(size_t)C3 * CH];
__device__ __align__(128) float g_wprojr[(size_t)CH * CH];

__device__ __forceinline__ uint32_t f2tf32(float f) {
    uint32_t r;
    asm("cvt.rna.tf32.f32 %0, %1;" : "=r"(r) : "f"(f));
    return r;
}
__device__ __forceinline__ float rndf(float f) { return __uint_as_float(f2tf32(f)); }

// f32x2 helpers
__device__ __forceinline__ unsigned long long pk2(float lo, float hi) {
    unsigned long long u;
    asm("mov.b64 %0, {%1, %2};" : "=l"(u) : "r"(__float_as_uint(lo)), "r"(__float_as_uint(hi)));
    return u;
}
__device__ __forceinline__ void upk2(unsigned long long u, float& lo, float& hi) {
    uint32_t a, b;
    asm("mov.b64 {%0, %1}, %2;" : "=r"(a), "=r"(b) : "l"(u));
    lo = __uint_as_float(a); hi = __uint_as_float(b);
}
__device__ __forceinline__ unsigned long long fma2(unsigned long long a,
                                                   unsigned long long b,
                                                   unsigned long long c) {
    unsigned long long d;
    asm("fma.rn.f32x2 %0, %1, %2, %3;" : "=l"(d) : "l"(a), "l"(b), "l"(c));
    return d;
}
__device__ __forceinline__ unsigned long long mul2(unsigned long long a,
                                                   unsigned long long b) {
    unsigned long long d;
    asm("mul.rn.f32x2 %0, %1, %2;" : "=l"(d) : "l"(a), "l"(b));
    return d;
}

__device__ __forceinline__ void ldsm4(uint32_t& r0, uint32_t& r1,
                                      uint32_t& r2, uint32_t& r3, uint32_t addr) {
    asm volatile("ldmatrix.sync.aligned.m8n8.x4.shared.b16 {%0,%1,%2,%3}, [%4];"
                 : "=r"(r0), "=r"(r1), "=r"(r2), "=r"(r3) : "r"(addr));
}
__device__ __forceinline__ void cp16(uint32_t saddr, const float* g, bool v) {
    asm volatile("cp.async.cg.shared.global [%0], [%1], 16, %2;"
                 :: "r"(saddr), "l"(g), "r"(v ? 16 : 0));
}

// ---------------------------------------------------------------------------
// Fused elementwise tf32-round copy over three buffers
// ---------------------------------------------------------------------------
__global__ __launch_bounds__(256)
void round_copy3_kernel(const float* __restrict__ a, float* __restrict__ oa, int na4,
                        const float* __restrict__ b, float* __restrict__ ob, int nb4,
                        const float* __restrict__ c, float* __restrict__ oc, int nc4)
{
    int total = na4 + nb4 + nc4;
    int i = blockIdx.x * 256 + threadIdx.x;
    int stride = gridDim.x * 256;
    for (; i < total; i += stride) {
        const float4* src;
        float4* dst;
        int idx = i;
        if (idx < na4) {
            src = reinterpret_cast<const float4*>(a);
            dst = reinterpret_cast<float4*>(oa);
        } else if ((idx -= na4) < nb4) {
            src = reinterpret_cast<const float4*>(b);
            dst = reinterpret_cast<float4*>(ob);
        } else {
            idx -= nb4;
            src = reinterpret_cast<const float4*>(c);
            dst = reinterpret_cast<float4*>(oc);
        }
        float4 v = src[idx];
        v.x = rndf(v.x); v.y = rndf(v.y); v.z = rndf(v.z); v.w = rndf(v.w);
        dst[idx] = v;
    }
}

// ---------------------------------------------------------------------------
// tf32 tensor-core NT GEMM, 3-stage cp.async, ldmatrix fragment loads.
// Smem per stage: row-major [row][128B], chunk index XOR-swizzled by row&7:
//   addr(row, kc) = row*128 + ((kc ^ (row & 7)) << 4)
//   C[m,n] = alpha * sum_k A[m*lda+k] * B[n*ldb+k]  (+ bias[n])
// 256 threads, warps 2(M) x 4(N). BK=32, K % 32 == 0. Inputs tf32-pre-rounded.
// ---------------------------------------------------------------------------
template<int BM, int BN, bool ROUND, int MINCTA>
__global__ __launch_bounds__(256, MINCTA)
void tc_gemm_nt(const float* __restrict__ A, const float* __restrict__ B,
                float* __restrict__ C, const float* __restrict__ bias,
                int M, int Nn, int K, int lda, int ldb, int ldc, float alpha,
                int Hdim,
                long long sAb, long long sAh,
                long long sBb, long long sBh,
                long long sCb, long long sCh)
{
    constexpr int BK = 32;
    constexpr int MI = BM / 2 / 16;
    constexpr int NJ = BN / 4 / 8;
    constexpr int ASTG = BM * 128;        // bytes per A stage
    constexpr int BSTG = BN * 128;        // bytes per B stage

    extern __shared__ uint32_t sm[];
    uint32_t* Asm = sm;                           // 3 stages A
    uint32_t* Bsm = sm + 3 * (ASTG / 4);          // 3 stages B

    const int z  = blockIdx.z;
    const int bb = z / Hdim;
    const int hh = z % Hdim;
    A += bb * sAb + hh * sAh;
    B += bb * sBb + hh * sBh;
    C += bb * sCb + hh * sCh;

    const int m0   = blockIdx.y * BM;
    const int n0   = blockIdx.x * BN;
    const int tid  = threadIdx.x;
    const int wid  = tid >> 5;
    const int lane = tid & 31;
    const int g    = lane >> 2;
    const int t    = lane & 3;
    const int wm   = (wid >> 2) * (BM / 2);
    const int wn   = (wid & 3) * (BN / 4);

    // producer indices
    const int pr  = tid >> 3;             // row 0..31
    const int pkc = tid & 7;              // k-chunk 0..7

    // consumer ldmatrix lane roles
    const int lrowA = (lane & 7) + ((lane >> 3) & 1) * 8;   // A: m within 16
    const int lkcA  = lane >> 4;                            // A: kc parity
    const int lrowB = (lane & 7) + ((lane >> 4) & 1) * 8;   // B: n within 16
    const int lkcB  = (lane >> 3) & 1;                      // B: kc parity

    const uint32_t sA = (uint32_t)__cvta_generic_to_shared(Asm);
    const uint32_t sB = (uint32_t)__cvta_generic_to_shared(Bsm);

    float acc[MI][NJ][4];
#pragma unroll
    for (int i = 0; i < MI; i++)
#pragma unroll
        for (int j = 0; j < NJ; j++)
#pragma unroll
            for (int q = 0; q < 4; q++) acc[i][j][q] = 0.f;

    const int niter = K / BK;

    auto issue = [&](int it) {
        const int k0 = it * BK;
        const int st = it % 3;
        const uint32_t aBase = sA + st * ASTG;
        const uint32_t bBase = sB + st * BSTG;
#pragma unroll
        for (int q = 0; q < BM / 32; q++) {
            int r  = pr + q * 32;
            int gm = m0 + r;
            bool v = gm < M;
            cp16(aBase + (r << 7) + (((pkc ^ (r & 7)) & 7) << 4),
                 A + (long long)(v ? gm : 0) * lda + k0 + pkc * 4, v);
        }
#pragma unroll
        for (int q = 0; q < BN / 32; q++) {
            int r  = pr + q * 32;
            int gn = n0 + r;
            bool v = gn < Nn;
            cp16(bBase + (r << 7) + (((pkc ^ (r & 7)) & 7) << 4),
                 B + (long long)(v ? gn : 0) * ldb + k0 + pkc * 4, v);
        }
        asm volatile("cp.async.commit_group;" ::: "memory");
    };

    issue(0);
    if (niter > 1) issue(1);

    for (int it = 0; it < niter; it++) {
        if (it + 2 <= niter) {
            asm volatile("cp.async.wait_group 1;" ::: "memory");
        } else {
            asm volatile("cp.async.wait_group 0;" ::: "memory");
        }
        __syncthreads();
        if (it + 2 < niter) issue(it + 2);

        const uint32_t aBase = sA + (it % 3) * ASTG;
        const uint32_t bBase = sB + (it % 3) * BSTG;

#pragma unroll
        for (int s = 0; s < 4; s++) {
            uint32_t af[MI][4];
            const int kcA = 2 * s + lkcA;
#pragma unroll
            for (int i = 0; i < MI; i++) {
                int m = wm + i * 16 + lrowA;
                ldsm4(af[i][0], af[i][1], af[i][2], af[i][3],
                      aBase + (m << 7) + (((kcA ^ (m & 7)) & 7) << 4));
            }
            uint32_t bf[NJ][2];
            const int kcB = 2 * s + lkcB;
#pragma unroll
            for (int jp = 0; jp < NJ / 2; jp++) {
                int n = wn + jp * 16 + lrowB;
                // Matrix order: (n0-7,kc even)=b0 lo, (n0-7,kc odd)=b1 lo,
                //               (n8-15,kc even)=b0 hi, (n8-15,kc odd)=b1 hi
                ldsm4(bf[2 * jp][0], bf[2 * jp][1],
                      bf[2 * jp + 1][0], bf[2 * jp + 1][1],
                      bBase + (n << 7) + (((kcB ^ (n & 7)) & 7) << 4));
            }
#pragma unroll
            for (int i = 0; i < MI; i++)
#pragma unroll
                for (int j = 0; j < NJ; j++) {
                    asm volatile(
                        "mma.sync.aligned.m16n8k8.row.col.f32.tf32.tf32.f32 "
                        "{%0,%1,%2,%3}, {%4,%5,%6,%7}, {%8,%9}, {%0,%1,%2,%3};"
                        : "+f"(acc[i][j][0]), "+f"(acc[i][j][1]),
                          "+f"(acc[i][j][2]), "+f"(acc[i][j][3])
                        : "r"(af[i][0]), "r"(af[i][1]), "r"(af[i][2]), "r"(af[i][3]),
                          "r"(bf[j][0]), "r"(bf[j][1]));
                }
        }
        // no trailing __syncthreads: top-of-loop barrier provides WAR safety
    }

    // ---- epilogue ----
#pragma unroll
    for (int i = 0; i < MI; i++) {
        int gm0 = m0 + wm + i * 16 + g;
        int gm1 = gm0 + 8;
#pragma unroll
        for (int j = 0; j < NJ; j++) {
            int gn = n0 + wn + j * 8 + 2 * t;
            float b0 = 0.f, b1 = 0.f;
            if (bias) {
                if (gn < Nn)     b0 = bias[gn];
                if (gn + 1 < Nn) b1 = bias[gn + 1];
            }
            float c0 = acc[i][j][0] * alpha + b0;
            float c1 = acc[i][j][1] * alpha + b1;
            float c2 = acc[i][j][2] * alpha + b0;
            float c3 = acc[i][j][3] * alpha + b1;
            if (ROUND) { c0 = rndf(c0); c1 = rndf(c1); c2 = rndf(c2); c3 = rndf(c3); }
            if (gm0 < M) {
                if (gn + 1 < Nn)
                    *reinterpret_cast<float2*>(C + (long long)gm0 * ldc + gn) = make_float2(c0, c1);
                else if (gn < Nn)
                    C[(long long)gm0 * ldc + gn] = c0;
            }
            if (gm1 < M) {
                if (gn + 1 < Nn)
                    *reinterpret_cast<float2*>(C + (long long)gm1 * ldc + gn) = make_float2(c2, c3);
                else if (gn < Nn)
                    C[(long long)gm1 * ldc + gn] = c2;
            }
        }
    }
}

// ---------------------------------------------------------------------------
// Transpose V: qkv[b,m, 2, h, d] -> vT[b,h, d, m] (ld = LD_P, pad stays 0)
// ---------------------------------------------------------------------------
__global__ __launch_bounds__(256)
void transpose_v_kernel(const float* __restrict__ qkv, float* __restrict__ vT)
{
    __shared__ float tile[32][33];
    const int dBase = (blockIdx.x & 1) * 32;
    const int mBase = blockIdx.y * 32;
    const int bh    = blockIdx.z;
    const int b     = bh / HH;
    const int h     = bh % HH;
    const int tx = threadIdx.x & 31;
    const int ty = threadIdx.x >> 5;

    const float* src = qkv + (long long)b * NTOK * C3 + 2 * CH + h * DD;
#pragma unroll
    for (int i = 0; i < 4; i++) {
        int m = mBase + ty + i * 8;
        if (m < NTOK)
            tile[ty + i * 8][tx] = src[(long long)m * C3 + dBase + tx];
    }
    __syncthreads();

    float* dst = vT + (long long)bh * DD * LD_P;
#pragma unroll
    for (int i = 0; i < 4; i++) {
        int d = dBase + ty + i * 8;
        int m = mBase + tx;
        if (m < NTOK)
            dst[(long long)d * LD_P + m] = tile[tx][ty + i * 8];
    }
}

// ---------------------------------------------------------------------------
// Fused talking-heads (register version, f32x2). P2 pad cols never written.
// Premix weights pre-scaled by log2e so softmax uses raw exp2f.
// ---------------------------------------------------------------------------
#define MIXT 320
#define LOG2E 1.4426950408889634f

__global__ __launch_bounds__(MIXT)
void mix_softmax_kernel(const float* __restrict__ S,
                        const float* __restrict__ Wpre,
                        const float* __restrict__ Wpost,
                        float* __restrict__ P2)
{
    __shared__ unsigned long long w2pre[HH * HH];
    __shared__ unsigned long long w2post[HH * HH];
    __shared__ float red[MIXT / 32][HH];
    __shared__ float smax[HH];
    __shared__ float sinv[HH];

    const int tid  = threadIdx.x;
    const int warp = tid >> 5;
    const int lane = tid & 31;
    const int bn = blockIdx.x;
    const int b  = bn / NTOK;
    const int n  = bn % NTOK;

    if (tid < HH * HH) {
        float wp = Wpre[tid] * LOG2E;   // fold log2e: T' = T*log2e
        float wq = Wpost[tid];
        w2pre[tid]  = pk2(wp, wp);
        w2post[tid] = pk2(wq, wq);
    }
    __syncthreads();

    const float* Sb = S + ((long long)b * HH * NTOK + n) * LD_S;
    const int m0 = tid;
    const int m1 = tid + MIXT;
    const bool v1 = (m1 < NTOK);

    unsigned long long s2[HH];
#pragma unroll
    for (int h = 0; h < HH; h++) {
        const float* p = Sb + (long long)h * NTOK * LD_S;
        float lo = p[m0];
        float hi = v1 ? p[m1] : 0.f;
        s2[h] = pk2(lo, hi);
    }

    unsigned long long t2[HH];
#pragma unroll
    for (int gg = 0; gg < HH; gg++) {
        unsigned long long accv = 0ull;
#pragma unroll
        for (int h = 0; h < HH; h++)
            accv = fma2(w2pre[gg * HH + h], s2[h], accv);
        t2[gg] = accv;
    }

    float lmax[HH];
#pragma unroll
    for (int gg = 0; gg < HH; gg++) {
        float lo, hi; upk2(t2[gg], lo, hi);
        lmax[gg] = v1 ? fmaxf(lo, hi) : lo;
    }
#pragma unroll
    for (int gg = 0; gg < HH; gg++)
#pragma unroll
        for (int o = 16; o > 0; o >>= 1)
            lmax[gg] = fmaxf(lmax[gg], __shfl_xor_sync(0xffffffffu, lmax[gg], o));
    if (lane == 0)
#pragma unroll
        for (int gg = 0; gg < HH; gg++) red[warp][gg] = lmax[gg];
    __syncthreads();
    if (tid < HH) {
        float mx = red[0][tid];
#pragma unroll
        for (int w = 1; w < MIXT / 32; w++) mx = fmaxf(mx, red[w][tid]);
        smax[tid] = mx;
    }
    __syncthreads();

    float lsum[HH];
#pragma unroll
    for (int gg = 0; gg < HH; gg++) {
        float lo, hi; upk2(t2[gg], lo, hi);
        // T' already scaled by log2e: exp(T-max) == exp2(T' - max')
        float el = exp2f(lo - smax[gg]);
        float eh = v1 ? exp2f(hi - smax[gg]) : 0.f;
        t2[gg] = pk2(el, eh);
        lsum[gg] = el + eh;
    }
#pragma unroll
    for (int gg = 0; gg < HH; gg++)
#pragma unroll
        for (int o = 16; o > 0; o >>= 1)
            lsum[gg] += __shfl_xor_sync(0xffffffffu, lsum[gg], o);
    if (lane == 0)
#pragma unroll
        for (int gg = 0; gg < HH; gg++) red[warp][gg] = lsum[gg];
    __syncthreads();
    if (tid < HH) {
        float s = red[0][tid];
#pragma unroll
        for (int w = 1; w < MIXT / 32; w++) s += red[w][tid];
        sinv[tid] = 1.f / s;
    }
    __syncthreads();

#pragma unroll
    for (int h = 0; h < HH; h++) {
        float iv = sinv[h];
        t2[h] = mul2(t2[h], pk2(iv, iv));
    }

    float* Pb = P2 + ((long long)b * HH * NTOK + n) * LD_P;
#pragma unroll
    for (int gg = 0; gg < HH; gg++) {
        unsigned long long accv = 0ull;
#pragma unroll
        for (int h = 0; h < HH; h++)
            accv = fma2(w2post[gg * HH + h], t2[h], accv);
        float lo, hi; upk2(accv, lo, hi);
        float* q = Pb + (long long)gg * NTOK * LD_P;
        q[m0] = rndf(lo);
        if (v1) q[m1] = rndf(hi);
        // pad cols [577,608) stay zero from static init; never written
    }
}

// ---------------------------------------------------------------------------
// Launch
// ---------------------------------------------------------------------------
extern "C" void kernel_launch(void* const* d_in, const int* in_sizes, int n_in,
                              void* d_out, int out_size)
{
    const float* x     = (const float*)d_in[0];
    const float* Wqkv  = (const float*)d_in[1];
    const float* Wproj = (const float*)d_in[2];
    const float* bproj = (const float*)d_in[3];
    const float* Wpre  = (const float*)d_in[4];
    const float* Wpost = (const float*)d_in[5];
    float* out = (float*)d_out;

    float *qkv, *S, *P2, *vT, *tmp, *xr, *wqkvr, *wprojr;
    cudaGetSymbolAddress((void**)&qkv, g_qkv);
    cudaGetSymbolAddress((void**)&S,   g_S);
    cudaGetSymbolAddress((void**)&P2,  g_P2);
    cudaGetSymbolAddress((void**)&vT,  g_vT);
    cudaGetSymbolAddress((void**)&tmp, g_tmp);
    cudaGetSymbolAddress((void**)&xr,  g_xr);
    cudaGetSymbolAddress((void**)&wqkvr, g_wqkvr);
    cudaGetSymbolAddress((void**)&wprojr, g_wprojr);

    // 0) tf32-round raw inputs (single fused launch)
    round_copy3_kernel<<<1024, 256>>>(
        x, xr, MROW * CH / 4,
        Wqkv, wqkvr, C3 * CH / 4,
        Wproj, wprojr, CH * CH / 4);

    const int smem_qkv   = 3 * (96 + 128) * 128;    // 86016
    const int smem_score = 3 * (128 + 128) * 128;   // 98304
    const int smem_av    = 3 * (128 + 64) * 128;    // 73728
    cudaFuncSetAttribute(tc_gemm_nt<96, 128, true, 2>,
                         cudaFuncAttributeMaxDynamicSharedMemorySize, smem_qkv);
    cudaFuncSetAttribute(tc_gemm_nt<96, 128, false, 2>,
                         cudaFuncAttributeMaxDynamicSharedMemorySize, smem_qkv);
    cudaFuncSetAttribute(tc_gemm_nt<128, 128, false, 2>,
                         cudaFuncAttributeMaxDynamicSharedMemorySize, smem_score);
    cudaFuncSetAttribute(tc_gemm_nt<128, 64, true, 3>,
                         cudaFuncAttributeMaxDynamicSharedMemorySize, smem_av);

    // 1) QKV GEMM: qkv = round(xr @ Wqkv^T)   [9232 x 2304], K=768, BM=96
    {
        dim3 grid(C3 / 128, (MROW + 95) / 96, 1);
        tc_gemm_nt<96, 128, true, 2><<<grid, 256, smem_qkv>>>(
            xr, wqkvr, qkv, nullptr,
            MROW, C3, CH, CH, CH, C3, 1.0f,
            1, 0, 0, 0, 0, 0, 0);
    }

    // 1.5) Transpose V -> vT[b,h,d,m]
    {
        dim3 grid(2, (NTOK + 31) / 32, NBH);
        transpose_v_kernel<<<grid, 256>>>(qkv, vT);
    }

    // 2) Scores: S = 1/8 * q @ k^T  (batched 192, M=N=577, K=64)
    //    BN=128 / MINCTA=2: measured-best config (R14, 94.4us).
    {
        dim3 grid((NTOK + 127) / 128, (NTOK + 127) / 128, NBH);
        tc_gemm_nt<128, 128, false, 2><<<grid, 256, smem_score>>>(
            qkv, qkv + CH, S, nullptr,
            NTOK, NTOK, DD,
            C3, C3, LD_S, 0.125f,
            HH,
            (long long)NTOK * C3, DD,
            (long long)NTOK * C3, DD,
            (long long)HH * NTOK * LD_S, (long long)NTOK * LD_S);
    }

    // 3) Fused Wpre-mix -> softmax -> Wpost-mix
    mix_softmax_kernel<<<MROW, MIXT>>>(S, Wpre, Wpost, P2);

    // 4) AV: tmp = round(P2 @ vT^T)   (K padded to 608), MINCTA=3
    {
        dim3 grid(1, (NTOK + 127) / 128, NBH);
        tc_gemm_nt<128, 64, true, 3><<<grid, 256, smem_av>>>(
            P2, vT, tmp, nullptr,
            NTOK, DD, LD_P,
            LD_P, LD_P, CH, 1.0f,
            HH,
            (long long)HH * NTOK * LD_P, (long long)NTOK * LD_P,
            (long long)HH * DD * LD_P,   (long long)DD * LD_P,
            (long long)NTOK * CH,        DD);
    }

    // 5) Projection: out = tmp @ Wproj^T + bproj   [9232 x 768], K=768, BM=96
    {
        dim3 grid(CH / 128, (MROW + 95) / 96, 1);
        tc_gemm_nt<96, 128, false, 2><<<grid, 256, smem_qkv>>>(
            tmp, wprojr, out, bproj,
            MROW, CH, CH, CH, CH, CH, 1.0f,
            1, 0, 0, 0, 0, 0, 0);
    }
}